// round 12
// baseline (speedup 1.0000x reference)
#include <cuda_runtime.h>
#include <cstdint>

// db2 inverse DWT (synthesis), polyphase. Block = one input row (256 threads).
// Input rows s, s+1 fetched as two 8KB cp.async.bulk copies into smem
// (burst-coherent DRAM reads); output rows staged in smem and written with
// one 8KB cp.async.bulk store (burst-coherent DRAM writes).
// x: [32, 512, 512, 4] NHWC f32  ->  y: [32, 1024, 1024, 1] f32

#define IN_H 512
#define IN_W 512
#define IN_B 32

__device__ __forceinline__ void quad2x2(
    const float4& v00, const float4& v01,
    const float4& v10, const float4& v11,
    const float L[2][2], const float G[2][2],
    float out[2][2])
{
    float a0[2] = { v00.x + v00.y, v10.x + v10.y };
    float a1[2] = { v01.x + v01.y, v11.x + v11.y };
    float z0[2] = { v00.z, v10.z };
    float z1[2] = { v01.z, v11.z };
    float w0[2] = { v00.w, v10.w };
    float w1[2] = { v01.w, v11.w };

    float r_az[2][2], r_w[2][2];
#pragma unroll
    for (int dv = 0; dv < 2; ++dv) {
#pragma unroll
        for (int ah = 0; ah < 2; ++ah) {
            float r = L[ah][0] * a0[dv];
            r = fmaf(L[ah][1], a1[dv], r);
            r = fmaf(G[ah][0], z0[dv], r);
            r = fmaf(G[ah][1], z1[dv], r);
            r_az[dv][ah] = r;
            r_w[dv][ah] = fmaf(G[ah][0], w0[dv], G[ah][1] * w1[dv]);
        }
    }
#pragma unroll
    for (int av = 0; av < 2; ++av) {
#pragma unroll
        for (int ah = 0; ah < 2; ++ah) {
            float r = L[av][0] * r_az[0][ah];
            r = fmaf(L[av][1], r_az[1][ah], r);
            r = fmaf(G[av][0], r_w[0][ah], r);
            r = fmaf(G[av][1], r_w[1][ah], r);
            out[av][ah] = r;
        }
    }
}

__global__ __launch_bounds__(256)
void idwt_db2_kernel(const float4* __restrict__ x, float4* __restrict__ y) {
    __shared__ alignas(16) float4 inA[512];   // input row s      (8KB)
    __shared__ alignas(16) float4 inB[512];   // input row s+1    (8KB)
    __shared__ alignas(16) float4 obuf[512];  // 2 output rows    (8KB)
    __shared__ alignas(8)  uint64_t mbar;

    const int u = threadIdx.x;          // 0..255 (col pair)
    const int s = blockIdx.x;           // 0..511
    const int b = blockIdx.z;           // 0..31

    uint32_t mb;
    asm("{ .reg .u64 t; cvta.to.shared.u64 t, %1; cvt.u32.u64 %0, t; }"
        : "=r"(mb) : "l"(&mbar));

    if (u == 0) {
        asm volatile("mbarrier.init.shared.b64 [%0], 1;" :: "r"(mb) : "memory");
    }
    __syncthreads();

    if (u == 0) {
        const int s1 = min(s + 1, IN_H - 1);
        const float4* src0 = &x[((size_t)b * IN_H + s ) * IN_W];
        const float4* src1 = &x[((size_t)b * IN_H + s1) * IN_W];
        uint32_t sA, sB;
        asm("{ .reg .u64 t; cvta.to.shared.u64 t, %1; cvt.u32.u64 %0, t; }"
            : "=r"(sA) : "l"(inA));
        asm("{ .reg .u64 t; cvta.to.shared.u64 t, %1; cvt.u32.u64 %0, t; }"
            : "=r"(sB) : "l"(inB));
        asm volatile("mbarrier.arrive.expect_tx.shared.b64 _, [%0], %1;"
                     :: "r"(mb), "r"(16384u) : "memory");
        asm volatile("cp.async.bulk.shared::cluster.global.mbarrier::complete_tx::bytes "
                     "[%0], [%1], %2, [%3];"
                     :: "r"(sA), "l"(src0), "r"(8192u), "r"(mb) : "memory");
        asm volatile("cp.async.bulk.shared::cluster.global.mbarrier::complete_tx::bytes "
                     "[%0], [%1], %2, [%3];"
                     :: "r"(sB), "l"(src1), "r"(8192u), "r"(mb) : "memory");
    }

    // Wait for both bulk loads (phase 0)
    {
        uint32_t done;
        asm volatile(
            "{\n\t"
            ".reg .pred p;\n\t"
            "mbarrier.try_wait.parity.acquire.cta.shared::cta.b64 p, [%1], 0;\n\t"
            "selp.b32 %0, 1, 0, p;\n\t"
            "}" : "=r"(done) : "r"(mb) : "memory");
        while (!done) {
            asm volatile(
                "{\n\t"
                ".reg .pred p;\n\t"
                "mbarrier.try_wait.parity.acquire.cta.shared::cta.b64 p, [%1], 0, 0x989680;\n\t"
                "selp.b32 %0, 1, 0, p;\n\t"
                "}" : "=r"(done) : "r"(mb) : "memory");
        }
    }

    const float h0 = 0.48296291314469025f;
    const float h1 = 0.83651630373780790f;
    const float h2 = 0.22414386804185735f;
    const float h3 = -0.12940952255092145f;
    const float L[2][2] = { { h2,  h0 }, {  h3,  h1 } };
    const float G[2][2] = { { h1,  h3 }, { -h0, -h2 } };

    const int t0 = 2 * u;
    const int t2 = min(t0 + 2, IN_W - 1);

    const float4 A0 = inA[t0], A1 = inA[t0 + 1], A2 = inA[t2];
    const float4 B0 = inB[t0], B1 = inB[t0 + 1], B2 = inB[t2];

    float oA[2][2], oB[2][2];
    quad2x2(A0, A1, B0, B1, L, G, oA);   // out cols 4u..4u+1
    quad2x2(A1, A2, B1, B2, L, G, oB);   // out cols 4u+2..4u+3

    obuf[u]       = make_float4(oA[0][0], oA[0][1], oB[0][0], oB[0][1]);
    obuf[u + 256] = make_float4(oA[1][0], oA[1][1], oB[1][0], oB[1][1]);
    __syncthreads();

    if (u == 0) {
        uint32_t so;
        asm("{ .reg .u64 t; cvta.to.shared.u64 t, %1; cvt.u32.u64 %0, t; }"
            : "=r"(so) : "l"(obuf));
        const float4* gdst = &y[((size_t)b * 1024 + 2 * s) * 256];
        asm volatile("fence.proxy.async.shared::cta;" ::: "memory");
        asm volatile("cp.async.bulk.global.shared::cta.bulk_group [%0], [%1], %2;"
                     :: "l"(gdst), "r"(so), "r"(8192u) : "memory");
        asm volatile("cp.async.bulk.commit_group;" ::: "memory");
        asm volatile("cp.async.bulk.wait_group.read 0;" ::: "memory");
        asm volatile("mbarrier.inval.shared.b64 [%0];" :: "r"(mb) : "memory");
    }
}

extern "C" void kernel_launch(void* const* d_in, const int* in_sizes, int n_in,
                              void* d_out, int out_size) {
    const float4* x = (const float4*)d_in[0];
    float4* y = (float4*)d_out;
    dim3 block(256, 1, 1);
    dim3 grid(IN_H, 1, IN_B);
    idwt_db2_kernel<<<grid, block>>>(x, y);
}

// round 13
// speedup vs baseline: 1.2412x; 1.2412x over previous
#include <cuda_runtime.h>
#include <cstdint>

// db2 inverse DWT (synthesis), polyphase. 2 input cols x 1 row per thread.
// Block = 128 threads = half an input row. Horizontal halo via warp shuffle
// (lane 31 loads it). Output staged in smem; two 2KB cp.async.bulk stores
// (one per output row segment). Finer CTA granularity than R9 for better
// SM load balance / occupancy.
// x: [32, 512, 512, 4] NHWC f32  ->  y: [32, 1024, 1024, 1] f32

#define IN_H 512
#define IN_W 512
#define IN_B 32

struct F8 { float4 a, b; };

__device__ __forceinline__ F8 ldg8(const float4* p) {
    unsigned r0,r1,r2,r3,r4,r5,r6,r7;
    asm volatile("ld.global.nc.v8.b32 {%0,%1,%2,%3,%4,%5,%6,%7}, [%8];"
                 : "=r"(r0), "=r"(r1), "=r"(r2), "=r"(r3),
                   "=r"(r4), "=r"(r5), "=r"(r6), "=r"(r7)
                 : "l"(p));
    F8 v;
    v.a = make_float4(__uint_as_float(r0), __uint_as_float(r1),
                      __uint_as_float(r2), __uint_as_float(r3));
    v.b = make_float4(__uint_as_float(r4), __uint_as_float(r5),
                      __uint_as_float(r6), __uint_as_float(r7));
    return v;
}

__device__ __forceinline__ float4 shfl_down_f4(float4 v) {
    float4 r;
    r.x = __shfl_down_sync(0xffffffffu, v.x, 1);
    r.y = __shfl_down_sync(0xffffffffu, v.y, 1);
    r.z = __shfl_down_sync(0xffffffffu, v.z, 1);
    r.w = __shfl_down_sync(0xffffffffu, v.w, 1);
    return r;
}

__device__ __forceinline__ void quad2x2(
    const float4& v00, const float4& v01,
    const float4& v10, const float4& v11,
    const float L[2][2], const float G[2][2],
    float out[2][2])
{
    float a0[2] = { v00.x + v00.y, v10.x + v10.y };
    float a1[2] = { v01.x + v01.y, v11.x + v11.y };
    float z0[2] = { v00.z, v10.z };
    float z1[2] = { v01.z, v11.z };
    float w0[2] = { v00.w, v10.w };
    float w1[2] = { v01.w, v11.w };

    float r_az[2][2], r_w[2][2];
#pragma unroll
    for (int dv = 0; dv < 2; ++dv) {
#pragma unroll
        for (int ah = 0; ah < 2; ++ah) {
            float r = L[ah][0] * a0[dv];
            r = fmaf(L[ah][1], a1[dv], r);
            r = fmaf(G[ah][0], z0[dv], r);
            r = fmaf(G[ah][1], z1[dv], r);
            r_az[dv][ah] = r;
            r_w[dv][ah] = fmaf(G[ah][0], w0[dv], G[ah][1] * w1[dv]);
        }
    }
#pragma unroll
    for (int av = 0; av < 2; ++av) {
#pragma unroll
        for (int ah = 0; ah < 2; ++ah) {
            float r = L[av][0] * r_az[0][ah];
            r = fmaf(L[av][1], r_az[1][ah], r);
            r = fmaf(G[av][0], r_w[0][ah], r);
            r = fmaf(G[av][1], r_w[1][ah], r);
            out[av][ah] = r;
        }
    }
}

__global__ __launch_bounds__(128)
void idwt_db2_kernel(const float4* __restrict__ x, float4* __restrict__ y) {
    __shared__ float4 buf[256];            // 2 half output rows, 4KB

    const int ut   = threadIdx.x;          // 0..127
    const int half = blockIdx.x & 1;       // which half of the row
    const int s    = blockIdx.x >> 1;      // 0..511
    const int b    = blockIdx.z;           // 0..31
    const int u    = half * 128 + ut;      // col pair 0..255
    const int lane = ut & 31;

    const float h0 = 0.48296291314469025f;
    const float h1 = 0.83651630373780790f;
    const float h2 = 0.22414386804185735f;
    const float h3 = -0.12940952255092145f;
    const float L[2][2] = { { h2,  h0 }, {  h3,  h1 } };
    const float G[2][2] = { { h1,  h3 }, { -h0, -h2 } };

    const int t0 = 2 * u;
    const int t2 = min(t0 + 2, IN_W - 1);
    const int s1 = min(s + 1, IN_H - 1);

    const size_t r0 = ((size_t)b * IN_H + s ) * IN_W;
    const size_t r1 = ((size_t)b * IN_H + s1) * IN_W;

    float4 Ah31, Bh31;
    if (lane == 31) {
        Ah31 = __ldg(&x[r0 + t2]);
        Bh31 = __ldg(&x[r1 + t2]);
    }
    const F8 A = ldg8(&x[r0 + t0]);
    const F8 B = ldg8(&x[r1 + t0]);

    float4 Ah = shfl_down_f4(A.a);
    float4 Bh = shfl_down_f4(B.a);
    if (lane == 31) { Ah = Ah31; Bh = Bh31; }

    float oA[2][2], oB[2][2];
    quad2x2(A.a, A.b, B.a, B.b, L, G, oA);   // out cols 4u..4u+1
    quad2x2(A.b, Ah,  B.b, Bh,  L, G, oB);   // out cols 4u+2..4u+3

    buf[ut]       = make_float4(oA[0][0], oA[0][1], oB[0][0], oB[0][1]);
    buf[ut + 128] = make_float4(oA[1][0], oA[1][1], oB[1][0], oB[1][1]);
    __syncthreads();

    if (ut == 0) {
        uint32_t saddr;
        asm("{ .reg .u64 t; cvta.to.shared.u64 t, %1; cvt.u32.u64 %0, t; }"
            : "=r"(saddr) : "l"(buf));
        // output rows 2s and 2s+1, this block's half (128 float4 each)
        const float4* g0 = &y[((size_t)b * 1024 + 2 * s) * 256 + half * 128];
        const float4* g1 = g0 + 256;
        asm volatile("fence.proxy.async.shared::cta;" ::: "memory");
        asm volatile("cp.async.bulk.global.shared::cta.bulk_group [%0], [%1], %2;"
                     :: "l"(g0), "r"(saddr), "r"(2048u) : "memory");
        asm volatile("cp.async.bulk.global.shared::cta.bulk_group [%0], [%1], %2;"
                     :: "l"(g1), "r"(saddr + 2048u), "r"(2048u) : "memory");
        asm volatile("cp.async.bulk.commit_group;" ::: "memory");
        asm volatile("cp.async.bulk.wait_group.read 0;" ::: "memory");
    }
}

extern "C" void kernel_launch(void* const* d_in, const int* in_sizes, int n_in,
                              void* d_out, int out_size) {
    const float4* x = (const float4*)d_in[0];
    float4* y = (float4*)d_out;
    dim3 block(128, 1, 1);
    dim3 grid(IN_H * 2, 1, IN_B);
    idwt_db2_kernel<<<grid, block>>>(x, y);
}

// round 14
// speedup vs baseline: 1.2421x; 1.0007x over previous
#include <cuda_runtime.h>
#include <cstdint>

// db2 inverse DWT (synthesis), polyphase. 2 input cols x 1 row per thread,
// block = one input row (256 threads). Horizontal halo via warp shuffle
// (only lane 31 loads it); vertical halo deduped in L2. Output staged in
// smem (2 full output rows = 8KB, gmem-contiguous) and written with one
// cp.async.bulk store per block for burst-coherent DRAM writes.
// x: [32, 512, 512, 4] NHWC f32  ->  y: [32, 1024, 1024, 1] f32
//
// R14 = confirmation re-bench of the R9 champion (43.2us).

#define IN_H 512
#define IN_W 512
#define IN_B 32

struct F8 { float4 a, b; };

__device__ __forceinline__ F8 ldg8(const float4* p) {
    unsigned r0,r1,r2,r3,r4,r5,r6,r7;
    asm volatile("ld.global.nc.v8.b32 {%0,%1,%2,%3,%4,%5,%6,%7}, [%8];"
                 : "=r"(r0), "=r"(r1), "=r"(r2), "=r"(r3),
                   "=r"(r4), "=r"(r5), "=r"(r6), "=r"(r7)
                 : "l"(p));
    F8 v;
    v.a = make_float4(__uint_as_float(r0), __uint_as_float(r1),
                      __uint_as_float(r2), __uint_as_float(r3));
    v.b = make_float4(__uint_as_float(r4), __uint_as_float(r5),
                      __uint_as_float(r6), __uint_as_float(r7));
    return v;
}

__device__ __forceinline__ float4 shfl_down_f4(float4 v) {
    float4 r;
    r.x = __shfl_down_sync(0xffffffffu, v.x, 1);
    r.y = __shfl_down_sync(0xffffffffu, v.y, 1);
    r.z = __shfl_down_sync(0xffffffffu, v.z, 1);
    r.w = __shfl_down_sync(0xffffffffu, v.w, 1);
    return r;
}

__device__ __forceinline__ void quad2x2(
    const float4& v00, const float4& v01,
    const float4& v10, const float4& v11,
    const float L[2][2], const float G[2][2],
    float out[2][2])
{
    float a0[2] = { v00.x + v00.y, v10.x + v10.y };
    float a1[2] = { v01.x + v01.y, v11.x + v11.y };
    float z0[2] = { v00.z, v10.z };
    float z1[2] = { v01.z, v11.z };
    float w0[2] = { v00.w, v10.w };
    float w1[2] = { v01.w, v11.w };

    float r_az[2][2], r_w[2][2];
#pragma unroll
    for (int dv = 0; dv < 2; ++dv) {
#pragma unroll
        for (int ah = 0; ah < 2; ++ah) {
            float r = L[ah][0] * a0[dv];
            r = fmaf(L[ah][1], a1[dv], r);
            r = fmaf(G[ah][0], z0[dv], r);
            r = fmaf(G[ah][1], z1[dv], r);
            r_az[dv][ah] = r;
            r_w[dv][ah] = fmaf(G[ah][0], w0[dv], G[ah][1] * w1[dv]);
        }
    }
#pragma unroll
    for (int av = 0; av < 2; ++av) {
#pragma unroll
        for (int ah = 0; ah < 2; ++ah) {
            float r = L[av][0] * r_az[0][ah];
            r = fmaf(L[av][1], r_az[1][ah], r);
            r = fmaf(G[av][0], r_w[0][ah], r);
            r = fmaf(G[av][1], r_w[1][ah], r);
            out[av][ah] = r;
        }
    }
}

__global__ __launch_bounds__(256)
void idwt_db2_kernel(const float4* __restrict__ x, float4* __restrict__ y) {
    __shared__ float4 buf[512];            // 2 output rows, 8KB, gmem-contiguous

    const int u    = threadIdx.x;          // 0..255 (col pair); block = one row
    const int s    = blockIdx.x;           // 0..511
    const int b    = blockIdx.z;           // 0..31
    const int lane = u & 31;

    const float h0 = 0.48296291314469025f;
    const float h1 = 0.83651630373780790f;
    const float h2 = 0.22414386804185735f;
    const float h3 = -0.12940952255092145f;
    const float L[2][2] = { { h2,  h0 }, {  h3,  h1 } };
    const float G[2][2] = { { h1,  h3 }, { -h0, -h2 } };

    const int t0 = 2 * u;
    const int t2 = min(t0 + 2, IN_W - 1);
    const int s1 = min(s + 1, IN_H - 1);

    const size_t r0 = ((size_t)b * IN_H + s ) * IN_W;
    const size_t r1 = ((size_t)b * IN_H + s1) * IN_W;

    float4 Ah31, Bh31;
    if (lane == 31) {
        Ah31 = __ldg(&x[r0 + t2]);
        Bh31 = __ldg(&x[r1 + t2]);
    }
    const F8 A = ldg8(&x[r0 + t0]);
    const F8 B = ldg8(&x[r1 + t0]);

    float4 Ah = shfl_down_f4(A.a);
    float4 Bh = shfl_down_f4(B.a);
    if (lane == 31) { Ah = Ah31; Bh = Bh31; }

    float oA[2][2], oB[2][2];
    quad2x2(A.a, A.b, B.a, B.b, L, G, oA);   // out cols 4u..4u+1
    quad2x2(A.b, Ah,  B.b, Bh,  L, G, oB);   // out cols 4u+2..4u+3

    buf[u]       = make_float4(oA[0][0], oA[0][1], oB[0][0], oB[0][1]);
    buf[u + 256] = make_float4(oA[1][0], oA[1][1], oB[1][0], oB[1][1]);
    __syncthreads();

    if (u == 0) {
        uint32_t saddr;
        asm("{ .reg .u64 t; cvta.to.shared.u64 t, %1; cvt.u32.u64 %0, t; }"
            : "=r"(saddr) : "l"(buf));
        const float4* gdst = &y[((size_t)b * 1024 + 2 * s) * 256];
        asm volatile("fence.proxy.async.shared::cta;" ::: "memory");
        asm volatile("cp.async.bulk.global.shared::cta.bulk_group [%0], [%1], %2;"
                     :: "l"(gdst), "r"(saddr), "r"(8192) : "memory");
        asm volatile("cp.async.bulk.commit_group;" ::: "memory");
        asm volatile("cp.async.bulk.wait_group.read 0;" ::: "memory");
    }
}

extern "C" void kernel_launch(void* const* d_in, const int* in_sizes, int n_in,
                              void* d_out, int out_size) {
    const float4* x = (const float4*)d_in[0];
    float4* y = (float4*)d_out;
    dim3 block(256, 1, 1);
    dim3 grid(IN_H, 1, IN_B);
    idwt_db2_kernel<<<grid, block>>>(x, y);
}

// round 15
// speedup vs baseline: 1.2578x; 1.0126x over previous
#include <cuda_runtime.h>
#include <cstdint>

// db2 inverse DWT (synthesis), polyphase. 2 input cols x 1 row per thread,
// block = one input row (256 threads). Horizontal halo via warp shuffle
// (only lane 31 loads it); vertical halo deduped in L2 — input lines marked
// L2::evict_last so the 128MB write stream cannot displace them before the
// row s+1 re-read. Output staged in smem (2 full output rows = 8KB,
// gmem-contiguous) and written with one cp.async.bulk store per block.
// x: [32, 512, 512, 4] NHWC f32  ->  y: [32, 1024, 1024, 1] f32

#define IN_H 512
#define IN_W 512
#define IN_B 32

struct F8 { float4 a, b; };

// 256-bit load, L2 evict-last (protect halo reuse). p must be 32B-aligned.
__device__ __forceinline__ F8 ldg8_el(const float4* p) {
    unsigned r0,r1,r2,r3,r4,r5,r6,r7;
    asm volatile("ld.global.nc.L2::evict_last.v8.b32 {%0,%1,%2,%3,%4,%5,%6,%7}, [%8];"
                 : "=r"(r0), "=r"(r1), "=r"(r2), "=r"(r3),
                   "=r"(r4), "=r"(r5), "=r"(r6), "=r"(r7)
                 : "l"(p));
    F8 v;
    v.a = make_float4(__uint_as_float(r0), __uint_as_float(r1),
                      __uint_as_float(r2), __uint_as_float(r3));
    v.b = make_float4(__uint_as_float(r4), __uint_as_float(r5),
                      __uint_as_float(r6), __uint_as_float(r7));
    return v;
}

__device__ __forceinline__ float4 shfl_down_f4(float4 v) {
    float4 r;
    r.x = __shfl_down_sync(0xffffffffu, v.x, 1);
    r.y = __shfl_down_sync(0xffffffffu, v.y, 1);
    r.z = __shfl_down_sync(0xffffffffu, v.z, 1);
    r.w = __shfl_down_sync(0xffffffffu, v.w, 1);
    return r;
}

__device__ __forceinline__ void quad2x2(
    const float4& v00, const float4& v01,
    const float4& v10, const float4& v11,
    const float L[2][2], const float G[2][2],
    float out[2][2])
{
    float a0[2] = { v00.x + v00.y, v10.x + v10.y };
    float a1[2] = { v01.x + v01.y, v11.x + v11.y };
    float z0[2] = { v00.z, v10.z };
    float z1[2] = { v01.z, v11.z };
    float w0[2] = { v00.w, v10.w };
    float w1[2] = { v01.w, v11.w };

    float r_az[2][2], r_w[2][2];
#pragma unroll
    for (int dv = 0; dv < 2; ++dv) {
#pragma unroll
        for (int ah = 0; ah < 2; ++ah) {
            float r = L[ah][0] * a0[dv];
            r = fmaf(L[ah][1], a1[dv], r);
            r = fmaf(G[ah][0], z0[dv], r);
            r = fmaf(G[ah][1], z1[dv], r);
            r_az[dv][ah] = r;
            r_w[dv][ah] = fmaf(G[ah][0], w0[dv], G[ah][1] * w1[dv]);
        }
    }
#pragma unroll
    for (int av = 0; av < 2; ++av) {
#pragma unroll
        for (int ah = 0; ah < 2; ++ah) {
            float r = L[av][0] * r_az[0][ah];
            r = fmaf(L[av][1], r_az[1][ah], r);
            r = fmaf(G[av][0], r_w[0][ah], r);
            r = fmaf(G[av][1], r_w[1][ah], r);
            out[av][ah] = r;
        }
    }
}

__global__ __launch_bounds__(256)
void idwt_db2_kernel(const float4* __restrict__ x, float4* __restrict__ y) {
    __shared__ float4 buf[512];            // 2 output rows, 8KB, gmem-contiguous

    const int u    = threadIdx.x;          // 0..255 (col pair); block = one row
    const int s    = blockIdx.x;           // 0..511
    const int b    = blockIdx.z;           // 0..31
    const int lane = u & 31;

    const float h0 = 0.48296291314469025f;
    const float h1 = 0.83651630373780790f;
    const float h2 = 0.22414386804185735f;
    const float h3 = -0.12940952255092145f;
    const float L[2][2] = { { h2,  h0 }, {  h3,  h1 } };
    const float G[2][2] = { { h1,  h3 }, { -h0, -h2 } };

    const int t0 = 2 * u;
    const int t2 = min(t0 + 2, IN_W - 1);
    const int s1 = min(s + 1, IN_H - 1);

    const size_t r0 = ((size_t)b * IN_H + s ) * IN_W;
    const size_t r1 = ((size_t)b * IN_H + s1) * IN_W;

    float4 Ah31, Bh31;
    if (lane == 31) {
        Ah31 = __ldg(&x[r0 + t2]);
        Bh31 = __ldg(&x[r1 + t2]);
    }
    const F8 A = ldg8_el(&x[r0 + t0]);
    const F8 B = ldg8_el(&x[r1 + t0]);

    float4 Ah = shfl_down_f4(A.a);
    float4 Bh = shfl_down_f4(B.a);
    if (lane == 31) { Ah = Ah31; Bh = Bh31; }

    float oA[2][2], oB[2][2];
    quad2x2(A.a, A.b, B.a, B.b, L, G, oA);   // out cols 4u..4u+1
    quad2x2(A.b, Ah,  B.b, Bh,  L, G, oB);   // out cols 4u+2..4u+3

    buf[u]       = make_float4(oA[0][0], oA[0][1], oB[0][0], oB[0][1]);
    buf[u + 256] = make_float4(oA[1][0], oA[1][1], oB[1][0], oB[1][1]);
    __syncthreads();

    if (u == 0) {
        uint32_t saddr;
        asm("{ .reg .u64 t; cvta.to.shared.u64 t, %1; cvt.u32.u64 %0, t; }"
            : "=r"(saddr) : "l"(buf));
        const float4* gdst = &y[((size_t)b * 1024 + 2 * s) * 256];
        asm volatile("fence.proxy.async.shared::cta;" ::: "memory");
        asm volatile("cp.async.bulk.global.shared::cta.bulk_group [%0], [%1], %2;"
                     :: "l"(gdst), "r"(saddr), "r"(8192) : "memory");
        asm volatile("cp.async.bulk.commit_group;" ::: "memory");
        asm volatile("cp.async.bulk.wait_group.read 0;" ::: "memory");
    }
}

extern "C" void kernel_launch(void* const* d_in, const int* in_sizes, int n_in,
                              void* d_out, int out_size) {
    const float4* x = (const float4*)d_in[0];
    float4* y = (float4*)d_out;
    dim3 block(256, 1, 1);
    dim3 grid(IN_H, 1, IN_B);
    idwt_db2_kernel<<<grid, block>>>(x, y);
}